// round 2
// baseline (speedup 1.0000x reference)
#include <cuda_runtime.h>
#include <cstdint>

#define NU 100000
#define NI 50000
#define NN 150000
#define NNZ_E 4800000
#define DIM 64
#define EPS_F 0.1f

// ---------------- static device scratch (allocation-free rule) ----------------
// __device__ globals are zero-initialized at module load; every launch restores
// the zero invariant it relies on (g_count re-zeroed by k_scanA), so replays
// are deterministic.
__device__ __align__(256) float g_ego0[(size_t)NN * DIM];   // 38.4 MB
__device__ __align__(256) float g_ego1[(size_t)NN * DIM];   // 38.4 MB
__device__ int  g_rowptr[NN + 1];
__device__ int  g_count[NN];       // zeroed at load; re-zeroed by k_scanA each launch
__device__ int  g_cursor[NN];      // preloaded with rowptr by k_scanB each launch
__device__ __align__(16) int2 g_edges[NNZ_E];               // 38.4 MB: {col, val-bits}
__device__ int  g_bsum[256];

// ---------------- Threefry-2x32, 20 rounds (exact JAX semantics) ----------------
__host__ __device__ inline void tf2x32(uint32_t k0, uint32_t k1,
                                       uint32_t x0, uint32_t x1,
                                       uint32_t& o0, uint32_t& o1) {
    uint32_t k2 = k0 ^ k1 ^ 0x1BD11BDAu;
    x0 += k0; x1 += k1;
#define TFR(r) { x0 += x1; x1 = (x1 << (r)) | (x1 >> (32 - (r))); x1 ^= x0; }
    TFR(13) TFR(15) TFR(26) TFR(6)   x0 += k1; x1 += k2 + 1u;
    TFR(17) TFR(29) TFR(16) TFR(24)  x0 += k2; x1 += k0 + 2u;
    TFR(13) TFR(15) TFR(26) TFR(6)   x0 += k0; x1 += k1 + 3u;
    TFR(17) TFR(29) TFR(16) TFR(24)  x0 += k1; x1 += k2 + 4u;
    TFR(13) TFR(15) TFR(26) TFR(6)   x0 += k2; x1 += k0 + 5u;
#undef TFR
    o0 = x0; o1 = x1;
}

__device__ __forceinline__ float u01f(uint32_t b) {
    return __uint_as_float((b >> 9) | 0x3f800000u) - 1.0f;
}

__device__ __forceinline__ float sgnf(float v) {
    return (v > 0.f) ? 1.f : ((v < 0.f) ? -1.f : 0.f);
}

// ---------------- kernel 1: fused concat + histogram ----------------
// grid exactly covers NNZ_E threads; first NN*DIM/4 also do the concat copy.
__global__ void k_init(const int* __restrict__ rows,
                       const float4* __restrict__ u, const float4* __restrict__ it) {
    int i = blockIdx.x * blockDim.x + threadIdx.x;
    atomicAdd(&g_count[rows[i]], 1);
    const int NC4 = NN * DIM / 4;       // 2.4M
    if (i < NC4) {
        const int NU4 = NU * DIM / 4;   // 1.6M
        float4 v = (i < NU4) ? u[i] : it[i - NU4];
        reinterpret_cast<float4*>(g_ego0)[i] = v;
    }
}

// ---------------- kernel 2: block-local exclusive scan (and re-zero counts) ----
__global__ void k_scanA() {
    __shared__ int sh[1024];
    int gid = blockIdx.x * 1024 + threadIdx.x;
    int v = 0;
    if (gid < NN) { v = g_count[gid]; g_count[gid] = 0; }   // restore invariant
    sh[threadIdx.x] = v;
    __syncthreads();
#pragma unroll
    for (int off = 1; off < 1024; off <<= 1) {
        int t = (threadIdx.x >= off) ? sh[threadIdx.x - off] : 0;
        __syncthreads();
        sh[threadIdx.x] += t;
        __syncthreads();
    }
    if (gid < NN) g_rowptr[gid] = sh[threadIdx.x] - v;      // block-local exclusive
    if (threadIdx.x == 1023) g_bsum[blockIdx.x] = sh[1023];
}

// ---------------- kernel 3: add block offsets, init cursor ----------------
#define SCAN_NB 147
__global__ void k_scanB() {
    __shared__ int sh[SCAN_NB];
    if (threadIdx.x < SCAN_NB) sh[threadIdx.x] = g_bsum[threadIdx.x];
    __syncthreads();
    int b = blockIdx.x;
    int offset = 0;
    for (int i = 0; i < b; i++) offset += sh[i];            // redundant, cheap
    int gid = b * 1024 + threadIdx.x;
    if (gid < NN) {
        int rp = g_rowptr[gid] + offset;
        g_rowptr[gid] = rp;
        g_cursor[gid] = rp;                                  // scatter cursor
    }
    if (b == SCAN_NB - 1 && threadIdx.x == 0)
        g_rowptr[NN] = offset + sh[SCAN_NB - 1];
}

// ---------------- kernel 4: counting-sort scatter ----------------
__global__ void k_scatter(const int* __restrict__ rows, const int* __restrict__ cols,
                          const float* __restrict__ vals) {
    int i = blockIdx.x * blockDim.x + threadIdx.x;          // grid covers NNZ_E
    int r = rows[i];
    int p = atomicAdd(&g_cursor[r], 1);
    g_edges[p] = make_int2(cols[i], __float_as_int(vals[i]));
}

// ---------------- kernels 5-7: fused SpMM gather + threefry noise ----------------
// 2 rows per warp: lanes 0-15 -> row 2w, lanes 16-31 -> row 2w+1.
// Each lane covers 4 dims (float4). Edges loaded cooperatively in chunks of 16
// (one coalesced int2 per lane, then shfl-broadcast) -> MLP ~16 gathers in flight.
// phase 0: src ego0, write ego1 + layer_out
// phase 1: src ego1, write ego0
// phase 2: src ego0, write mean_out = (ego1 + ego0 + e3)/3
__global__ void __launch_bounds__(256) k_hop(int phase, uint32_t hk0, uint32_t hk1,
                                             float* __restrict__ mean_out,
                                             float* __restrict__ layer_out) {
    const float* __restrict__ xin = (phase == 1) ? g_ego1 : g_ego0;

    int w    = (blockIdx.x * blockDim.x + threadIdx.x) >> 5;  // warp id, grid exact
    int lane = threadIdx.x & 31;
    int grp  = lane & 16;                  // 0 or 16
    int l16  = lane & 15;
    unsigned hmask = 0xffffu << grp;       // half-warp mask
    int r = 2 * w + (grp >> 4);            // row handled by this half-warp

    int s = g_rowptr[r];
    int e = g_rowptr[r + 1];

    float4 acc = make_float4(0.f, 0.f, 0.f, 0.f);
    for (int base = s; base < e; base += 16) {
        int j = base + l16;
        int2 ed = (j < e) ? g_edges[j] : make_int2(0, 0);
        int cnt = e - base; if (cnt > 16) cnt = 16;
#pragma unroll
        for (int t = 0; t < 16; t++) {
            if (t < cnt) {
                int   cc = __shfl_sync(hmask, ed.x, grp + t);
                float vv = __int_as_float(__shfl_sync(hmask, ed.y, grp + t));
                float4 xv = *reinterpret_cast<const float4*>(
                    xin + (size_t)cc * DIM + 4 * l16);
                acc.x = fmaf(vv, xv.x, acc.x);
                acc.y = fmaf(vv, xv.y, acc.y);
                acc.z = fmaf(vv, xv.z, acc.z);
                acc.w = fmaf(vv, xv.w, acc.w);
            }
        }
    }

    // noise: partitionable threefry, bits = out0 ^ out1 of block (0, idx)
    uint32_t idx = (uint32_t)r * DIM + 4u * (uint32_t)l16;
    float un[4];
#pragma unroll
    for (int q = 0; q < 4; q++) {
        uint32_t o0, o1;
        tf2x32(hk0, hk1, 0u, idx + (uint32_t)q, o0, o1);
        un[q] = u01f(o0 ^ o1);
    }
    float ss = fmaf(un[0], un[0], fmaf(un[1], un[1], fmaf(un[2], un[2], un[3] * un[3])));
#pragma unroll
    for (int off = 8; off; off >>= 1)
        ss += __shfl_xor_sync(hmask, ss, off);
    float f = EPS_F * rsqrtf(ss);

    float4 ev;
    ev.x = acc.x + sgnf(acc.x) * un[0] * f;
    ev.y = acc.y + sgnf(acc.y) * un[1] * f;
    ev.z = acc.z + sgnf(acc.z) * un[2] * f;
    ev.w = acc.w + sgnf(acc.w) * un[3] * f;

    size_t p = (size_t)r * DIM + 4 * l16;
    if (phase == 0) {
        *reinterpret_cast<float4*>(g_ego1 + p)     = ev;
        *reinterpret_cast<float4*>(layer_out + p)  = ev;
    } else if (phase == 1) {
        *reinterpret_cast<float4*>(g_ego0 + p)     = ev;
    } else {
        float4 e1 = *reinterpret_cast<const float4*>(g_ego1 + p);
        float4 e2 = *reinterpret_cast<const float4*>(g_ego0 + p);
        float4 m;
        m.x = (e1.x + e2.x + ev.x) * (1.f / 3.f);
        m.y = (e1.y + e2.y + ev.y) * (1.f / 3.f);
        m.z = (e1.z + e2.z + ev.z) * (1.f / 3.f);
        m.w = (e1.w + e2.w + ev.w) * (1.f / 3.f);
        *reinterpret_cast<float4*>(mean_out + p) = m;
    }
}

// ---------------- launch ----------------
extern "C" void kernel_launch(void* const* d_in, const int* in_sizes, int n_in,
                              void* d_out, int out_size) {
    const float* user = (const float*)d_in[0];
    const float* item = (const float*)d_in[1];
    const int*   rows = (const int*)d_in[2];
    const int*   cols = (const int*)d_in[3];
    const float* vals = (const float*)d_in[4];
    float* out = (float*)d_out;
    float* mean_out  = out;                       // user_all ++ item_all
    float* layer_out = out + (size_t)NN * DIM;    // user_layer ++ item_layer

    // per-hop keys: fold_in(key(42), k) == threefry((0,42),(0,k))
    uint32_t hk0[3], hk1[3];
    for (int k = 0; k < 3; k++)
        tf2x32(0u, 42u, 0u, (uint32_t)k, hk0[k], hk1[k]);

    k_init<<<NNZ_E / 256, 256>>>(rows, (const float4*)user, (const float4*)item);
    k_scanA<<<SCAN_NB, 1024>>>();
    k_scanB<<<SCAN_NB, 1024>>>();
    k_scatter<<<NNZ_E / 256, 256>>>(rows, cols, vals);

    // 75000 warps (2 rows each) = 9375 blocks x 256
    k_hop<<<9375, 256>>>(0, hk0[0], hk1[0], mean_out, layer_out);
    k_hop<<<9375, 256>>>(1, hk0[1], hk1[1], mean_out, layer_out);
    k_hop<<<9375, 256>>>(2, hk0[2], hk1[2], mean_out, layer_out);
}

// round 3
// speedup vs baseline: 1.0352x; 1.0352x over previous
#include <cuda_runtime.h>
#include <cstdint>

#define NU 100000
#define NI 50000
#define NN 150000
#define NNZ_E 4800000
#define DIM 64
#define EPS_F 0.1f

// ---------------- static device scratch (allocation-free rule) ----------------
// __device__ globals are zero-initialized at module load; every launch restores
// the zero invariant it relies on (g_count re-zeroed by k_scanA).
__device__ __align__(256) float g_ego0[(size_t)NN * DIM];   // 38.4 MB
__device__ __align__(256) float g_ego1[(size_t)NN * DIM];   // 38.4 MB
__device__ int  g_rowptr[NN + 1];
__device__ int  g_count[NN];       // zeroed at load; re-zeroed by k_scanA each launch
__device__ int  g_cursor[NN];      // preloaded with rowptr by k_scanB each launch
__device__ __align__(16) int2 g_edges[NNZ_E];               // 38.4 MB: {col, val-bits}
__device__ int  g_bsum[256];

// ---------------- Threefry-2x32, 20 rounds (exact JAX semantics) ----------------
__host__ __device__ inline void tf2x32(uint32_t k0, uint32_t k1,
                                       uint32_t x0, uint32_t x1,
                                       uint32_t& o0, uint32_t& o1) {
    uint32_t k2 = k0 ^ k1 ^ 0x1BD11BDAu;
    x0 += k0; x1 += k1;
#define TFR(r) { x0 += x1; x1 = (x1 << (r)) | (x1 >> (32 - (r))); x1 ^= x0; }
    TFR(13) TFR(15) TFR(26) TFR(6)   x0 += k1; x1 += k2 + 1u;
    TFR(17) TFR(29) TFR(16) TFR(24)  x0 += k2; x1 += k0 + 2u;
    TFR(13) TFR(15) TFR(26) TFR(6)   x0 += k0; x1 += k1 + 3u;
    TFR(17) TFR(29) TFR(16) TFR(24)  x0 += k1; x1 += k2 + 4u;
    TFR(13) TFR(15) TFR(26) TFR(6)   x0 += k2; x1 += k0 + 5u;
#undef TFR
    o0 = x0; o1 = x1;
}

__device__ __forceinline__ float u01f(uint32_t b) {
    return __uint_as_float((b >> 9) | 0x3f800000u) - 1.0f;
}

__device__ __forceinline__ float sgnf(float v) {
    return (v > 0.f) ? 1.f : ((v < 0.f) ? -1.f : 0.f);
}

// ---------------- kernel 1: fused histogram (2 edges/thread) + concat ----------
// grid: 9375 x 256 = 2.4M threads. Each does 2 histogram edges (int2 load) and
// one float4 concat element (2.4M float4 = NN*DIM).
__global__ void k_init(const int2* __restrict__ rows2,
                       const float4* __restrict__ u, const float4* __restrict__ it) {
    int t = blockIdx.x * blockDim.x + threadIdx.x;          // [0, 2.4M)
    int2 rr = rows2[t];                                     // edges 2t, 2t+1
    atomicAdd(&g_count[rr.x], 1);
    atomicAdd(&g_count[rr.y], 1);
    const int NU4 = NU * DIM / 4;                           // 1.6M
    float4 v = (t < NU4) ? u[t] : it[t - NU4];
    reinterpret_cast<float4*>(g_ego0)[t] = v;
}

// ---------------- kernel 2: block-local exclusive scan (and re-zero counts) ----
__global__ void k_scanA() {
    __shared__ int sh[1024];
    int gid = blockIdx.x * 1024 + threadIdx.x;
    int v = 0;
    if (gid < NN) { v = g_count[gid]; g_count[gid] = 0; }   // restore invariant
    sh[threadIdx.x] = v;
    __syncthreads();
#pragma unroll
    for (int off = 1; off < 1024; off <<= 1) {
        int t = (threadIdx.x >= off) ? sh[threadIdx.x - off] : 0;
        __syncthreads();
        sh[threadIdx.x] += t;
        __syncthreads();
    }
    if (gid < NN) g_rowptr[gid] = sh[threadIdx.x] - v;      // block-local exclusive
    if (threadIdx.x == 1023) g_bsum[blockIdx.x] = sh[1023];
}

// ---------------- kernel 3: add block offsets, init cursor ----------------
#define SCAN_NB 147
__global__ void k_scanB() {
    __shared__ int sh[SCAN_NB];
    if (threadIdx.x < SCAN_NB) sh[threadIdx.x] = g_bsum[threadIdx.x];
    __syncthreads();
    int b = blockIdx.x;
    int offset = 0;
    for (int i = 0; i < b; i++) offset += sh[i];            // redundant, cheap
    int gid = b * 1024 + threadIdx.x;
    if (gid < NN) {
        int rp = g_rowptr[gid] + offset;
        g_rowptr[gid] = rp;
        g_cursor[gid] = rp;                                  // scatter cursor
    }
    if (b == SCAN_NB - 1 && threadIdx.x == 0)
        g_rowptr[NN] = offset + sh[SCAN_NB - 1];
}

// ---------------- kernel 4: counting-sort scatter (2 edges/thread) ----------------
__global__ void k_scatter(const int2* __restrict__ rows2,
                          const int2* __restrict__ cols2,
                          const float2* __restrict__ vals2) {
    int t = blockIdx.x * blockDim.x + threadIdx.x;          // [0, 2.4M)
    int2   rr = rows2[t];
    int2   cc = cols2[t];
    float2 vv = vals2[t];
    // two independent atomic->store chains in flight
    int p0 = atomicAdd(&g_cursor[rr.x], 1);
    int p1 = atomicAdd(&g_cursor[rr.y], 1);
    g_edges[p0] = make_int2(cc.x, __float_as_int(vv.x));
    g_edges[p1] = make_int2(cc.y, __float_as_int(vv.y));
}

// ---------------- kernels 5-7: fused SpMM gather + threefry noise ----------------
// One warp per row, lane handles dims (2*lane, 2*lane+1). Edge loads are warp-
// uniform (single sector, broadcast). Unroll 8 => ~8 gathers in flight per warp.
// phase 0: src ego0 -> write ego1 + layer_out
// phase 1: src ego1 -> write ego0
// phase 2: src ego0 -> read ego1, ego0; write mean_out = (ego1 + ego0 + e3)/3
__global__ void __launch_bounds__(256) k_hop(int phase, uint32_t hk0, uint32_t hk1,
                                             float* __restrict__ mean_out,
                                             float* __restrict__ layer_out) {
    const float* __restrict__ xin = (phase == 1) ? g_ego1 : g_ego0;

    int w    = (blockIdx.x * blockDim.x + threadIdx.x) >> 5;   // row, grid exact
    int lane = threadIdx.x & 31;

    int s = g_rowptr[w];
    int e = g_rowptr[w + 1];
    float acc0 = 0.f, acc1 = 0.f;
#pragma unroll 8
    for (int j = s; j < e; j++) {
        int2 cv = g_edges[j];                                   // uniform broadcast
        const float2 xv = *reinterpret_cast<const float2*>(
            xin + (size_t)cv.x * DIM + 2 * lane);
        float v = __int_as_float(cv.y);
        acc0 = fmaf(v, xv.x, acc0);
        acc1 = fmaf(v, xv.y, acc1);
    }

    // noise: partitionable threefry, bits = out0 ^ out1 of block (0, idx)
    uint32_t idx = (uint32_t)w * DIM + 2u * (uint32_t)lane;
    uint32_t a0, a1, b0, b1;
    tf2x32(hk0, hk1, 0u, idx,      a0, a1);
    tf2x32(hk0, hk1, 0u, idx + 1u, b0, b1);
    float u0 = u01f(a0 ^ a1);
    float u1 = u01f(b0 ^ b1);

    float ss = fmaf(u0, u0, u1 * u1);
#pragma unroll
    for (int off = 16; off; off >>= 1)
        ss += __shfl_xor_sync(0xffffffffu, ss, off);
    float f = EPS_F * rsqrtf(ss);

    float e0 = acc0 + sgnf(acc0) * u0 * f;
    float e1 = acc1 + sgnf(acc1) * u1 * f;

    size_t p = (size_t)w * DIM + 2 * lane;
    float2 ev = make_float2(e0, e1);
    if (phase == 0) {
        *reinterpret_cast<float2*>(g_ego1 + p)    = ev;
        *reinterpret_cast<float2*>(layer_out + p) = ev;
    } else if (phase == 1) {
        *reinterpret_cast<float2*>(g_ego0 + p)    = ev;
    } else {
        float2 e1v = *reinterpret_cast<const float2*>(g_ego1 + p);
        float2 e2v = *reinterpret_cast<const float2*>(g_ego0 + p);
        float2 m;
        m.x = (e1v.x + e2v.x + ev.x) * (1.f / 3.f);
        m.y = (e1v.y + e2v.y + ev.y) * (1.f / 3.f);
        *reinterpret_cast<float2*>(mean_out + p) = m;
    }
}

// ---------------- launch ----------------
extern "C" void kernel_launch(void* const* d_in, const int* in_sizes, int n_in,
                              void* d_out, int out_size) {
    const float* user = (const float*)d_in[0];
    const float* item = (const float*)d_in[1];
    const int*   rows = (const int*)d_in[2];
    const int*   cols = (const int*)d_in[3];
    const float* vals = (const float*)d_in[4];
    float* out = (float*)d_out;
    float* mean_out  = out;                       // user_all ++ item_all
    float* layer_out = out + (size_t)NN * DIM;    // user_layer ++ item_layer

    // per-hop keys: fold_in(key(42), k) == threefry((0,42),(0,k))
    uint32_t hk0[3], hk1[3];
    for (int k = 0; k < 3; k++)
        tf2x32(0u, 42u, 0u, (uint32_t)k, hk0[k], hk1[k]);

    // build: 2.4M threads, 2 edges each
    k_init<<<9375, 256>>>((const int2*)rows, (const float4*)user, (const float4*)item);
    k_scanA<<<SCAN_NB, 1024>>>();
    k_scanB<<<SCAN_NB, 1024>>>();
    k_scatter<<<9375, 256>>>((const int2*)rows, (const int2*)cols, (const float2*)vals);

    // 150000 warps (1 row each) = 18750 blocks x 256
    k_hop<<<18750, 256>>>(0, hk0[0], hk1[0], mean_out, layer_out);
    k_hop<<<18750, 256>>>(1, hk0[1], hk1[1], mean_out, layer_out);
    k_hop<<<18750, 256>>>(2, hk0[2], hk1[2], mean_out, layer_out);
}

// round 4
// speedup vs baseline: 1.1336x; 1.0951x over previous
#include <cuda_runtime.h>
#include <cstdint>

#define NU 100000
#define NI 50000
#define NN 150000
#define NNZ_E 4800000
#define DIM 64
#define EPS_F 0.1f
#define SCAN_NB 147

// ---------------- static device scratch (allocation-free rule) ----------------
// Zero-initialized at module load; every launch restores the invariants it
// relies on (g_count re-zeroed by k_scan, g_flag re-zeroed by k_init).
__device__ __align__(256) float g_ego0[(size_t)NN * DIM];   // 38.4 MB
__device__ int  g_rowptr[NN + 1];
__device__ int  g_count[NN];                 // zero before k_init; re-zeroed in k_scan
__device__ int  g_flag[SCAN_NB];             // lookback flags; zeroed in k_init
__device__ __align__(16) int2 g_edges[NNZ_E];               // 38.4 MB: {col, val-bits}
__device__ __align__(8)  int  g_rank[NNZ_E];                // 19.2 MB: rank within row

// ---------------- Threefry-2x32, 20 rounds (exact JAX semantics) ----------------
__host__ __device__ inline void tf2x32(uint32_t k0, uint32_t k1,
                                       uint32_t x0, uint32_t x1,
                                       uint32_t& o0, uint32_t& o1) {
    uint32_t k2 = k0 ^ k1 ^ 0x1BD11BDAu;
    x0 += k0; x1 += k1;
#define TFR(r) { x0 += x1; x1 = (x1 << (r)) | (x1 >> (32 - (r))); x1 ^= x0; }
    TFR(13) TFR(15) TFR(26) TFR(6)   x0 += k1; x1 += k2 + 1u;
    TFR(17) TFR(29) TFR(16) TFR(24)  x0 += k2; x1 += k0 + 2u;
    TFR(13) TFR(15) TFR(26) TFR(6)   x0 += k0; x1 += k1 + 3u;
    TFR(17) TFR(29) TFR(16) TFR(24)  x0 += k1; x1 += k2 + 4u;
    TFR(13) TFR(15) TFR(26) TFR(6)   x0 += k2; x1 += k0 + 5u;
#undef TFR
    o0 = x0; o1 = x1;
}

__device__ __forceinline__ float u01f(uint32_t b) {
    return __uint_as_float((b >> 9) | 0x3f800000u) - 1.0f;
}

__device__ __forceinline__ float sgnf(float v) {
    return (v > 0.f) ? 1.f : ((v < 0.f) ? -1.f : 0.f);
}

// ---------------- kernel 1: histogram + rank memo + concat + flag reset ----------
// grid: 9375 x 256 = 2.4M threads; 2 edges each; one float4 concat element each.
__global__ void k_init(const int2* __restrict__ rows2,
                       const float4* __restrict__ u, const float4* __restrict__ it) {
    int t = blockIdx.x * blockDim.x + threadIdx.x;          // [0, 2.4M)
    if (blockIdx.x == 0 && threadIdx.x < SCAN_NB) g_flag[threadIdx.x] = 0;
    int2 rr = rows2[t];                                     // edges 2t, 2t+1
    int r0 = atomicAdd(&g_count[rr.x], 1);                  // rank within row
    int r1 = atomicAdd(&g_count[rr.y], 1);
    reinterpret_cast<int2*>(g_rank)[t] = make_int2(r0, r1); // coalesced memo
    const int NU4 = NU * DIM / 4;                           // 1.6M
    float4 v = (t < NU4) ? u[t] : it[t - NU4];
    reinterpret_cast<float4*>(g_ego0)[t] = v;
}

// ---------------- kernel 2: single-pass scan (decoupled lookback) ----------------
// 147 blocks x 1024 (all co-resident on 152 SMs -> lookback cannot deadlock).
__global__ void __launch_bounds__(1024) k_scan() {
    __shared__ int sh[1024];
    __shared__ int sh_exc;
    int gid = blockIdx.x * 1024 + threadIdx.x;
    int v = 0;
    if (gid < NN) { v = g_count[gid]; g_count[gid] = 0; }   // restore invariant
    sh[threadIdx.x] = v;
    __syncthreads();
#pragma unroll
    for (int off = 1; off < 1024; off <<= 1) {
        int t = (threadIdx.x >= off) ? sh[threadIdx.x - off] : 0;
        __syncthreads();
        sh[threadIdx.x] += t;
        __syncthreads();
    }
    int total = sh[1023];                                   // block aggregate
    if (threadIdx.x < 32) {
        int lane = threadIdx.x;
        if (lane == 0)                                      // publish aggregate fast
            atomicExch(&g_flag[blockIdx.x], (total << 2) | 1);
        int exc = 0;
        int p = (int)blockIdx.x - 1;
        while (p >= 0) {                                    // warp-parallel lookback
            int idx = p - lane;
            int f = 0;
            if (idx >= 0) {
                do { f = *(volatile int*)&g_flag[idx]; } while ((f & 3) == 0);
            }
            unsigned inc = __ballot_sync(0xffffffffu, idx >= 0 && (f & 3) == 2);
            int stop = inc ? (__ffs(inc) - 1) : 32;
            int c = (idx >= 0 && lane <= stop) ? (f >> 2) : 0;
#pragma unroll
            for (int o = 16; o; o >>= 1) c += __shfl_xor_sync(0xffffffffu, c, o);
            exc += c;
            if (inc) break;
            p -= 32;
        }
        if (lane == 0) {
            atomicExch(&g_flag[blockIdx.x], ((exc + total) << 2) | 2);
            sh_exc = exc;
        }
    }
    __syncthreads();
    int base = sh_exc;
    if (gid < NN) g_rowptr[gid] = base + sh[threadIdx.x] - v;   // exclusive
    if (blockIdx.x == SCAN_NB - 1 && threadIdx.x == 1023)
        g_rowptr[NN] = base + total;
}

// ---------------- kernel 3: atomic-free counting-sort scatter ----------------
__global__ void k_scatter(const int2* __restrict__ rows2,
                          const int2* __restrict__ cols2,
                          const float2* __restrict__ vals2) {
    int t = blockIdx.x * blockDim.x + threadIdx.x;          // [0, 2.4M)
    int2   rr = rows2[t];
    int2   cc = cols2[t];
    float2 vv = vals2[t];
    int2   rk = reinterpret_cast<const int2*>(g_rank)[t];
    int p0 = g_rowptr[rr.x] + rk.x;                         // rowptr is L2-hot (600KB)
    int p1 = g_rowptr[rr.y] + rk.y;
    g_edges[p0] = make_int2(cc.x, __float_as_int(vv.x));
    g_edges[p1] = make_int2(cc.y, __float_as_int(vv.y));
}

// ---------------- kernels 4-6: fused SpMM gather + threefry noise ----------------
// One warp per row; lane covers dims (2*lane, 2*lane+1); edge loads warp-uniform.
// phase 0: xin = g_ego0     -> write layer_out           (e1, also hop-1 input)
// phase 1: xin = layer_out  -> write g_ego0              (e2)
// phase 2: xin = g_ego0     -> mean_out = (layer + ego0 + e3) / 3
__global__ void __launch_bounds__(256) k_hop(int phase, uint32_t hk0, uint32_t hk1,
                                             float* __restrict__ mean_out,
                                             const float* __restrict__ layer_in,
                                             float* __restrict__ layer_out) {
    const float* __restrict__ xin = (phase == 1) ? layer_in : g_ego0;

    int w    = (blockIdx.x * blockDim.x + threadIdx.x) >> 5;   // row, grid exact
    int lane = threadIdx.x & 31;

    int s = g_rowptr[w];
    int e = g_rowptr[w + 1];
    float acc0 = 0.f, acc1 = 0.f;
#pragma unroll 4
    for (int j = s; j < e; j++) {
        int2 cv = g_edges[j];                                   // uniform broadcast
        const float2 xv = *reinterpret_cast<const float2*>(
            xin + (size_t)cv.x * DIM + 2 * lane);
        float v = __int_as_float(cv.y);
        acc0 = fmaf(v, xv.x, acc0);
        acc1 = fmaf(v, xv.y, acc1);
    }

    // noise: partitionable threefry, bits = out0 ^ out1 of block (0, idx)
    uint32_t idx = (uint32_t)w * DIM + 2u * (uint32_t)lane;
    uint32_t a0, a1, b0, b1;
    tf2x32(hk0, hk1, 0u, idx,      a0, a1);
    tf2x32(hk0, hk1, 0u, idx + 1u, b0, b1);
    float u0 = u01f(a0 ^ a1);
    float u1 = u01f(b0 ^ b1);

    float ss = fmaf(u0, u0, u1 * u1);
#pragma unroll
    for (int off = 16; off; off >>= 1)
        ss += __shfl_xor_sync(0xffffffffu, ss, off);
    float f = EPS_F * rsqrtf(ss);

    float e0 = acc0 + sgnf(acc0) * u0 * f;
    float e1 = acc1 + sgnf(acc1) * u1 * f;

    size_t p = (size_t)w * DIM + 2 * lane;
    float2 ev = make_float2(e0, e1);
    if (phase == 0) {
        *reinterpret_cast<float2*>(layer_out + p) = ev;
    } else if (phase == 1) {
        *reinterpret_cast<float2*>(g_ego0 + p)    = ev;
    } else {
        float2 lv = *reinterpret_cast<const float2*>(layer_in + p);
        float2 e2 = *reinterpret_cast<const float2*>(g_ego0 + p);
        float2 m;
        m.x = (lv.x + e2.x + ev.x) * (1.f / 3.f);
        m.y = (lv.y + e2.y + ev.y) * (1.f / 3.f);
        *reinterpret_cast<float2*>(mean_out + p) = m;
    }
}

// ---------------- launch ----------------
extern "C" void kernel_launch(void* const* d_in, const int* in_sizes, int n_in,
                              void* d_out, int out_size) {
    const float* user = (const float*)d_in[0];
    const float* item = (const float*)d_in[1];
    const int*   rows = (const int*)d_in[2];
    const int*   cols = (const int*)d_in[3];
    const float* vals = (const float*)d_in[4];
    float* out = (float*)d_out;
    float* mean_out  = out;                       // user_all ++ item_all
    float* layer_out = out + (size_t)NN * DIM;    // user_layer ++ item_layer

    // per-hop keys: fold_in(key(42), k) == threefry((0,42),(0,k))
    uint32_t hk0[3], hk1[3];
    for (int k = 0; k < 3; k++)
        tf2x32(0u, 42u, 0u, (uint32_t)k, hk0[k], hk1[k]);

    k_init<<<9375, 256>>>((const int2*)rows, (const float4*)user, (const float4*)item);
    k_scan<<<SCAN_NB, 1024>>>();
    k_scatter<<<9375, 256>>>((const int2*)rows, (const int2*)cols, (const float2*)vals);

    // 150000 warps (1 row each) = 18750 blocks x 256; hop0 is launch #4 (profiled)
    k_hop<<<18750, 256>>>(0, hk0[0], hk1[0], mean_out, layer_out, layer_out);
    k_hop<<<18750, 256>>>(1, hk0[1], hk1[1], mean_out, layer_out, layer_out);
    k_hop<<<18750, 256>>>(2, hk0[2], hk1[2], mean_out, layer_out, layer_out);
}